// round 1
// baseline (speedup 1.0000x reference)
#include <cuda_runtime.h>

#define NQ   4096
#define MT   16384
#define DD   32
#define OUTD 16
#define KNB  5
#define EPSV 1e-6f

#define QT     32            // queries per block
#define CT     128           // points per chunk
#define SPLIT  8             // M splits
#define PPB    (MT / SPLIT)  // 2048 points per block
#define CHUNKS (PPB / CT)    // 16
#define TSS    132           // tsT row stride (floats), pad for bank spread
#define QSS    34            // qs2 row stride (u64)

typedef unsigned long long u64;

// scratch: per (query, split) top-5 candidates
__device__ float g_pval[NQ * SPLIT * KNB];
__device__ int   g_pidx[NQ * SPLIT * KNB];

__device__ __forceinline__ u64 fma2(u64 a, u64 b, u64 c) {
    u64 d;
    asm("fma.rn.f32x2 %0, %1, %2, %3;" : "=l"(d) : "l"(a), "l"(b), "l"(c));
    return d;
}

// sorted ascending top-5-smallest insert (V[0] smallest .. V[4] largest kept)
#define INS(V, I, s, g) do {                                                   \
    if ((s) < V[4]) {                                                          \
        V[4] = (s); I[4] = (g);                                                \
        if (V[4] < V[3]) { float t_=V[3]; V[3]=V[4]; V[4]=t_; int u_=I[3]; I[3]=I[4]; I[4]=u_; } \
        if (V[3] < V[2]) { float t_=V[2]; V[2]=V[3]; V[3]=t_; int u_=I[2]; I[2]=I[3]; I[3]=u_; } \
        if (V[2] < V[1]) { float t_=V[1]; V[1]=V[2]; V[2]=t_; int u_=I[1]; I[1]=I[2]; I[2]=u_; } \
        if (V[1] < V[0]) { float t_=V[0]; V[0]=V[1]; V[1]=t_; int u_=I[0]; I[0]=I[1]; I[1]=u_; } \
    } } while (0)

__global__ void __launch_bounds__(128) idw_part_kernel(
    const float* __restrict__ xg,    // [NQ, DD]
    const float* __restrict__ txg,   // [MT, DD]
    const float* __restrict__ wg)    // [DD]
{
    __shared__ float sinv[DD];
    __shared__ float qn[QT];
    __shared__ __align__(16) u64 qs2[DD * QSS];        // f32x2-splat queries, [d][q]
    __shared__ __align__(16) char sbuf[QT * 80 * 8];   // union: tsT+tn | cand lists

    float* tsT  = (float*)sbuf;                        // [DD][TSS]
    float* tn   = (float*)(sbuf + DD * TSS * 4);       // [CT]
    float* cval = (float*)sbuf;                        // [QT][80]
    int*   cidx = (int*)(sbuf + QT * 80 * 4);          // [QT][80]

    const int tid = threadIdx.x;
    const int ty  = tid >> 4;      // 0..7
    const int txl = tid & 15;      // 0..15
    const int bid = blockIdx.x;
    const int qg  = bid >> 3;      // query group 0..127
    const int sp  = bid & 7;       // split 0..7
    const int qbase  = qg * QT;
    const int pbase0 = sp * PPB;

    if (tid < DD) sinv[tid] = expf(-wg[tid]);
    __syncthreads();

    // stage scaled queries as f32x2 splats, transposed [d][q]
    for (int idx = tid; idx < QT * DD; idx += 128) {
        int q = idx >> 5, d = idx & 31;
        float v = xg[(qbase + q) * DD + d] * sinv[d];
        unsigned int b = __float_as_uint(v);
        qs2[d * QSS + q] = ((u64)b << 32) | (u64)b;
    }
    __syncthreads();
    if (tid < QT) {
        float s = 0.f;
        #pragma unroll
        for (int d = 0; d < DD; d++) {
            float v = __uint_as_float((unsigned int)qs2[d * QSS + tid]);
            s += v * v;
        }
        qn[tid] = s;
    }

    // per-thread top-5 (smallest s) for 4 queries
    float tv[4][KNB];
    int   tix[4][KNB];
    #pragma unroll
    for (int i = 0; i < 4; i++)
        #pragma unroll
        for (int k = 0; k < KNB; k++) { tv[i][k] = 3.0e38f; tix[i][k] = 0; }

    const u64 M2 = 0xC0000000C0000000ULL;  // (-2.0f, -2.0f)

    #pragma unroll 1
    for (int c = 0; c < CHUNKS; c++) {
        const int pbase = pbase0 + c * CT;
        __syncthreads();   // protect tn reads of previous chunk epilogue

        // stage scaled train chunk transposed [d][p]
        {
            const int d  = tid & 31;
            const int p0 = tid >> 5;
            const float si = sinv[d];
            const float* src = txg + (size_t)pbase * DD;
            #pragma unroll
            for (int k = 0; k < CT / 4; k++) {
                int p = p0 + 4 * k;
                tsT[d * TSS + p] = src[p * DD + d] * si;
            }
        }
        __syncthreads();

        // per-point squared norms
        {
            float s = 0.f;
            #pragma unroll
            for (int d = 0; d < DD; d++) {
                float v = tsT[d * TSS + tid];
                s += v * v;
            }
            tn[tid] = s;
        }
        __syncthreads();

        // register-tiled dot products: 4 queries x 8 points, f32x2 packed
        u64 acc[4][4];
        #pragma unroll
        for (int i = 0; i < 4; i++)
            #pragma unroll
            for (int j = 0; j < 4; j++) acc[i][j] = 0ULL;

        #pragma unroll
        for (int d = 0; d < DD; d++) {
            const float* trow = &tsT[d * TSS];
            ulonglong2 A0 = *(const ulonglong2*)(trow + txl * 4);
            ulonglong2 A1 = *(const ulonglong2*)(trow + 64 + txl * 4);
            u64 ap[4] = { A0.x, A0.y, A1.x, A1.y };
            const u64* qd = &qs2[d * QSS + ty * 4];
            ulonglong2 Q0 = *(const ulonglong2*)(qd);
            ulonglong2 Q1 = *(const ulonglong2*)(qd + 2);
            u64 aq[4] = { Q0.x, Q0.y, Q1.x, Q1.y };
            #pragma unroll
            for (int i = 0; i < 4; i++) {
                #pragma unroll
                for (int j = 0; j < 4; j++)
                    acc[i][j] = fma2(aq[i], ap[j], acc[i][j]);
            }
        }

        // epilogue: s = tn - 2*dot, guarded top-5 insert
        ulonglong2 T0 = *(const ulonglong2*)(tn + txl * 4);
        ulonglong2 T1 = *(const ulonglong2*)(tn + 64 + txl * 4);
        u64 tns[4] = { T0.x, T0.y, T1.x, T1.y };
        int gb[4]  = { pbase + txl * 4,      pbase + txl * 4 + 2,
                       pbase + 64 + txl * 4, pbase + 64 + txl * 4 + 2 };
        #pragma unroll
        for (int i = 0; i < 4; i++) {
            #pragma unroll
            for (int j = 0; j < 4; j++) {
                u64 s2 = fma2(acc[i][j], M2, tns[j]);
                float slo = __uint_as_float((unsigned int)s2);
                float shi = __uint_as_float((unsigned int)(s2 >> 32));
                int g = gb[j];
                INS(tv[i], tix[i], slo, g);
                INS(tv[i], tix[i], shi, g + 1);
            }
        }
    }

    // block-level merge: 16 tx-threads x 5 candidates per query
    __syncthreads();
    #pragma unroll
    for (int i = 0; i < 4; i++) {
        int q = ty * 4 + i;
        #pragma unroll
        for (int k = 0; k < KNB; k++) {
            cval[q * 80 + txl * KNB + k] = tv[i][k];
            cidx[q * 80 + txl * KNB + k] = tix[i][k];
        }
    }
    __syncthreads();

    if (tid < QT) {
        float v[KNB]; int ix[KNB];
        #pragma unroll
        for (int k = 0; k < KNB; k++) { v[k] = 3.0e38f; ix[k] = 0; }
        for (int cc = 0; cc < 80; cc++) {
            float s = cval[tid * 80 + cc];
            int   g = cidx[tid * 80 + cc];
            INS(v, ix, s, g);
        }
        float qnn = qn[tid];
        int gq = qbase + tid;
        int base = (gq * SPLIT + sp) * KNB;
        #pragma unroll
        for (int k = 0; k < KNB; k++) {
            g_pval[base + k] = qnn + v[k];   // full squared distance
            g_pidx[base + k] = ix[k];
        }
    }
}

__global__ void idw_final_kernel(const float* __restrict__ tyg,  // [MT, OUTD]
                                 float* __restrict__ outg)       // [NQ, OUTD]
{
    int gq = blockIdx.x * blockDim.x + threadIdx.x;
    if (gq >= NQ) return;

    const int base = gq * SPLIT * KNB;
    float v[KNB]; int ix[KNB];
    #pragma unroll
    for (int k = 0; k < KNB; k++) { v[k] = 3.0e38f; ix[k] = 0; }
    for (int c = 0; c < SPLIT * KNB; c++) {
        float s = g_pval[base + c];
        int   g = g_pidx[base + c];
        INS(v, ix, s, g);
    }
    const float v5 = v[KNB - 1];   // 5th smallest sq == threshold

    float o[OUTD];
    #pragma unroll
    for (int k = 0; k < OUTD; k++) o[k] = 0.f;
    float wsum = 0.f;

    for (int c = 0; c < SPLIT * KNB; c++) {
        float s = g_pval[base + c];
        if (s <= v5) {   // matches reference dinv >= min_val (incl. exact ties)
            float dinv = rsqrtf(fmaxf(s, 0.f) + EPSV);
            wsum += dinv;
            const float* yr = tyg + (size_t)g_pidx[base + c] * OUTD;
            #pragma unroll
            for (int k = 0; k < OUTD; k++) o[k] += dinv * yr[k];
        }
    }
    float wi = 1.f / wsum;
    float4* dst = (float4*)(outg + (size_t)gq * OUTD);
    #pragma unroll
    for (int k = 0; k < 4; k++) {
        float4 r;
        r.x = o[k * 4 + 0] * wi; r.y = o[k * 4 + 1] * wi;
        r.z = o[k * 4 + 2] * wi; r.w = o[k * 4 + 3] * wi;
        dst[k] = r;
    }
}

extern "C" void kernel_launch(void* const* d_in, const int* in_sizes, int n_in,
                              void* d_out, int out_size)
{
    // identify inputs by element count (robust to ordering)
    const float *xg = nullptr, *txg = nullptr, *tyg = nullptr, *wg = nullptr;
    for (int i = 0; i < n_in; i++) {
        switch (in_sizes[i]) {
            case NQ * DD:   xg  = (const float*)d_in[i]; break;  // 131072
            case MT * DD:   txg = (const float*)d_in[i]; break;  // 524288
            case MT * OUTD: tyg = (const float*)d_in[i]; break;  // 262144
            case DD:        wg  = (const float*)d_in[i]; break;  // 32
        }
    }
    float* outg = (float*)d_out;

    idw_part_kernel<<< (NQ / QT) * SPLIT, 128 >>>(xg, txg, wg);
    idw_final_kernel<<< (NQ + 255) / 256, 256 >>>(tyg, outg);
}